// round 4
// baseline (speedup 1.0000x reference)
#include <cuda_runtime.h>

#define DIM 768
#define NH 12
#define HD 64
#define BATCH 2
#define SEQ 2048
#define ROWS (BATCH*SEQ)      // 4096
#define SCALE 0.125f
#define LN_EPS 1e-5f

// ---------------- scratch (tf32-rounded payloads) ----------------
__device__ float g_xn[ROWS*DIM];
__device__ float g_q [BATCH*NH*SEQ*HD];   // [bh][n][d], pre-scaled by SCALE
__device__ float g_k [BATCH*NH*SEQ*HD];
__device__ float g_v [BATCH*NH*SEQ*HD];
__device__ float g_att[ROWS*DIM];
__device__ float g_wq[DIM*3*DIM];
__device__ float g_wo[DIM*DIM];

// ---------------- helpers ----------------
__device__ __forceinline__ unsigned f2tf(float x) {
    unsigned u; asm("cvt.rna.tf32.f32 %0, %1;" : "=r"(u) : "f"(x)); return u;
}
__device__ __forceinline__ float f2tff(float x) { return __uint_as_float(f2tf(x)); }

__device__ __forceinline__ void mma8(float* c, const unsigned* a, const unsigned* b) {
    asm volatile("mma.sync.aligned.m16n8k8.row.col.f32.tf32.tf32.f32 "
        "{%0,%1,%2,%3}, {%4,%5,%6,%7}, {%8,%9}, {%0,%1,%2,%3};"
        : "+f"(c[0]), "+f"(c[1]), "+f"(c[2]), "+f"(c[3])
        : "r"(a[0]), "r"(a[1]), "r"(a[2]), "r"(a[3]), "r"(b[0]), "r"(b[1]));
}

__device__ __forceinline__ void cp16(float* dst, const float* src) {
    unsigned d = (unsigned)__cvta_generic_to_shared(dst);
    asm volatile("cp.async.cg.shared.global [%0], [%1], 16;" :: "r"(d), "l"(src));
}
#define CPCOMMIT  asm volatile("cp.async.commit_group;" ::: "memory")
#define CPWAIT0   asm volatile("cp.async.wait_group 0;"  ::: "memory")
#define CPWAIT1   asm volatile("cp.async.wait_group 1;"  ::: "memory")

// ---------------- weight pre-convert ----------------
__global__ void wcvt_kernel(const float4* __restrict__ src, int n4, int which) {
    float4* dst = (float4*)(which ? g_wo : g_wq);
    int i = blockIdx.x * blockDim.x + threadIdx.x;
    if (i < n4) {
        float4 v = src[i];
        v.x = f2tff(v.x); v.y = f2tff(v.y); v.z = f2tff(v.z); v.w = f2tff(v.w);
        dst[i] = v;
    }
}

// ---------------- LayerNorm ----------------
__global__ void ln_kernel(const float* __restrict__ x,
                          const float* __restrict__ gamma,
                          const float* __restrict__ beta) {
    int row = blockIdx.x;
    const float* xr = x + (size_t)row * DIM;
    int t = threadIdx.x;
    float v0 = xr[t], v1 = xr[t+256], v2 = xr[t+512];
    __shared__ float red[8];

    float s = v0 + v1 + v2;
    #pragma unroll
    for (int o = 16; o > 0; o >>= 1) s += __shfl_xor_sync(0xffffffffu, s, o);
    if ((t & 31) == 0) red[t >> 5] = s;
    __syncthreads();
    if (t < 8) {
        float r = red[t];
        #pragma unroll
        for (int o = 4; o > 0; o >>= 1) r += __shfl_xor_sync(0xffu, r, o);
        if (t == 0) red[0] = r;
    }
    __syncthreads();
    float mean = red[0] * (1.0f / DIM);
    float d0 = v0 - mean, d1 = v1 - mean, d2 = v2 - mean;
    __syncthreads();

    float ss = d0*d0 + d1*d1 + d2*d2;
    #pragma unroll
    for (int o = 16; o > 0; o >>= 1) ss += __shfl_xor_sync(0xffffffffu, ss, o);
    if ((t & 31) == 0) red[t >> 5] = ss;
    __syncthreads();
    if (t < 8) {
        float r = red[t];
        #pragma unroll
        for (int o = 4; o > 0; o >>= 1) r += __shfl_xor_sync(0xffu, r, o);
        if (t == 0) red[0] = r;
    }
    __syncthreads();
    float rstd = rsqrtf(red[0] * (1.0f / DIM) + LN_EPS);

    float* o = g_xn + (size_t)row * DIM;
    o[t]     = f2tff(d0 * rstd * gamma[t]     + beta[t]);
    o[t+256] = f2tff(d1 * rstd * gamma[t+256] + beta[t+256]);
    o[t+512] = f2tff(d2 * rstd * gamma[t+512] + beta[t+512]);
}

// ---------------- TF32 GEMM, 64x64 warp tiles, 3-stage cp.async ----------------
// MODE 1: 128x256 block, 8 warps, A=g_xn B=g_wq -> scatter g_q/g_k/g_v
// MODE 0: 128x128 block, 4 warps, A=g_att B=g_wo -> C row-major
template<int MODE>
__global__ void __launch_bounds__(MODE ? 256 : 128, MODE ? 1 : 2)
gemm_kernel(const float* __restrict__ bias, float* __restrict__ C, int Ncols) {
    constexpr int T    = MODE ? 256 : 128;
    constexpr int BN   = MODE ? 256 : 128;
    constexpr int BSTR = BN + 8;
    constexpr int AS_STG = 128*36;
    constexpr int BS_STG = 32*BSTR;

    const float* A  = MODE ? g_xn : g_att;
    const float* Bm = MODE ? g_wq : g_wo;
    extern __shared__ __align__(16) float smg[];
    float* Asb = smg;
    float* Bsb = smg + 3*AS_STG;

    int tid = threadIdx.x;
    int wid = tid >> 5, lane = tid & 31;
    int g = lane >> 2, t = lane & 3;
    int wm = MODE ? (wid >> 2)*64 : (wid >> 1)*64;
    int wn = MODE ? (wid & 3)*64  : (wid & 1)*64;
    int m0 = blockIdx.y * 128, n0 = blockIdx.x * BN;

    float acc[4][8][4];
    #pragma unroll
    for (int i = 0; i < 4; i++)
        #pragma unroll
        for (int j = 0; j < 8; j++)
            #pragma unroll
            for (int r = 0; r < 4; r++) acc[i][j][r] = 0.0f;

    #define GPREF(k0, st) do { \
        _Pragma("unroll") \
        for (int l = 0; l < 1024/T; l++) { int idx = tid + l*T; int row = idx >> 3, cf = idx & 7; \
            cp16(Asb + (st)*AS_STG + row*36 + cf*4, A + (size_t)(m0+row)*DIM + (k0) + cf*4); } \
        _Pragma("unroll") \
        for (int l = 0; l < (8*BN)/T; l++) { int idx = tid + l*T; \
            int row = idx / (BN/4), cf = idx % (BN/4); \
            cp16(Bsb + (st)*BS_STG + row*BSTR + cf*4, Bm + (size_t)((k0)+row)*Ncols + n0 + cf*4); } \
    } while (0)

    GPREF(0, 0);  CPCOMMIT;
    GPREF(32, 1); CPCOMMIT;

    const int NK = DIM/32;   // 24
    for (int kt = 0; kt < NK; kt++) {
        CPWAIT1;
        __syncthreads();
        if (kt + 2 < NK) { int pst = (kt+2) % 3; GPREF((kt+2)*32, pst); }
        CPCOMMIT;

        int st = kt % 3;
        const float* Ast = Asb + st*AS_STG;
        const float* Bst = Bsb + st*BS_STG;

        #pragma unroll
        for (int ks = 0; ks < 4; ks++) {
            int kb = ks*8;
            unsigned af[4][4], bf[8][2];
            #pragma unroll
            for (int i = 0; i < 4; i++) {
                int r = wm + i*16 + g;
                af[i][0] = __float_as_uint(Ast[r*36     + kb+t  ]);
                af[i][1] = __float_as_uint(Ast[(r+8)*36 + kb+t  ]);
                af[i][2] = __float_as_uint(Ast[r*36     + kb+t+4]);
                af[i][3] = __float_as_uint(Ast[(r+8)*36 + kb+t+4]);
            }
            #pragma unroll
            for (int j = 0; j < 8; j++) {
                int c = wn + j*8 + g;
                bf[j][0] = __float_as_uint(Bst[(kb+t  )*BSTR + c]);
                bf[j][1] = __float_as_uint(Bst[(kb+t+4)*BSTR + c]);
            }
            #pragma unroll
            for (int i = 0; i < 4; i++)
                #pragma unroll
                for (int j = 0; j < 8; j++)
                    mma8(acc[i][j], af[i], bf[j]);
        }
        __syncthreads();
    }

    #pragma unroll
    for (int j = 0; j < 8; j++) {
        int c0 = n0 + wn + j*8 + 2*t;
        float b0 = bias[c0], b1 = bias[c0+1];
        if (MODE == 0) {
            #pragma unroll
            for (int i = 0; i < 4; i++) {
                int ra = m0 + wm + i*16 + g;
                float2 va = make_float2(acc[i][j][0] + b0, acc[i][j][1] + b1);
                float2 vb = make_float2(acc[i][j][2] + b0, acc[i][j][3] + b1);
                *(float2*)(C + (size_t)ra*Ncols + c0) = va;
                *(float2*)(C + (size_t)(ra+8)*Ncols + c0) = vb;
            }
        } else {
            int which = c0 / DIM;
            int cc = c0 - which*DIM;
            int h = cc >> 6, dd = cc & 63;
            float* dst = (which == 0) ? g_q : (which == 1) ? g_k : g_v;
            float mul = (which == 0) ? SCALE : 1.0f;
            #pragma unroll
            for (int i = 0; i < 4; i++) {
                int ra = m0 + wm + i*16 + g;
                int bb = ra >> 11, n = ra & 2047;
                size_t base = ((size_t)((bb*NH + h)*SEQ + n))*HD + dd;
                float2 va = make_float2(f2tff((acc[i][j][0] + b0)*mul),
                                        f2tff((acc[i][j][1] + b1)*mul));
                float2 vb = make_float2(f2tff((acc[i][j][2] + b0)*mul),
                                        f2tff((acc[i][j][3] + b1)*mul));
                *(float2*)(dst + base) = va;
                *(float2*)(dst + base + (size_t)8*HD) = vb;
            }
        }
    }
    #undef GPREF
}

// ---------------- TF32 flash attention: 256q block, 8 warps x 32q, 64k tiles ----------------
#define QST 68
#define PST 68
#define KST 68
#define VST 72
#define KSTG (64*KST)
#define VSTG (64*VST)
#define ATTN_SMEM ((256*QST + 256*PST + 2*KSTG + 2*VSTG)*4)   // 210944 B

__global__ void __launch_bounds__(256, 1) attn_kernel() {
    extern __shared__ __align__(16) float sm[];
    float* Qs  = sm;                   // [256][68]
    float* Ps  = Qs + 256*QST;         // [256][68]
    float* Ksb = Ps + 256*PST;         // [2][64][68]
    float* Vsb = Ksb + 2*KSTG;         // [2][64][72]

    int qt = blockIdx.x, bh = blockIdx.y;
    const float* Qg = g_q + (size_t)bh*SEQ*HD;
    const float* Kg = g_k + (size_t)bh*SEQ*HD;
    const float* Vg = g_v + (size_t)bh*SEQ*HD;

    int tid = threadIdx.x, wid = tid >> 5, lane = tid & 31;
    int g = lane >> 2, t = lane & 3;
    int qbase = wid*32;

    #define APREF(kt, st) do { \
        _Pragma("unroll") \
        for (int l = 0; l < 4; l++) { int idx = tid + l*256; int row = idx >> 4, cf = idx & 15; \
            cp16(Ksb + (st)*KSTG + row*KST + cf*4, Kg + ((size_t)((kt)*64+row))*HD + cf*4); \
            cp16(Vsb + (st)*VSTG + row*VST + cf*4, Vg + ((size_t)((kt)*64+row))*HD + cf*4); } \
    } while (0)

    APREF(0, 0);
    #pragma unroll
    for (int l = 0; l < 16; l++) {
        int idx = tid + l*256;
        int row = idx >> 4, cf = idx & 15;
        cp16(Qs + row*QST + cf*4, Qg + ((size_t)(qt*256+row))*HD + cf*4);
    }
    CPCOMMIT;

    float mA[2][2], lA[2][2];
    float O[2][8][4];
    #pragma unroll
    for (int mt = 0; mt < 2; mt++) {
        mA[mt][0] = mA[mt][1] = -1e30f;
        lA[mt][0] = lA[mt][1] = 0.0f;
        #pragma unroll
        for (int dt = 0; dt < 8; dt++)
            #pragma unroll
            for (int r = 0; r < 4; r++) O[mt][dt][r] = 0.0f;
    }

    const int NT = SEQ/64;
    for (int kt = 0; kt < NT; kt++) {
        CPWAIT0;
        __syncthreads();
        if (kt + 1 < NT) { APREF(kt+1, (kt+1)&1); }
        CPCOMMIT;

        const float* Ks = Ksb + (kt&1)*KSTG;
        const float* Vs = Vsb + (kt&1)*VSTG;

        // S = Q K^T : 2 m-tiles x 8 n-tiles per warp, shared K fragments
        float s[2][8][4];
        #pragma unroll
        for (int mt = 0; mt < 2; mt++)
            #pragma unroll
            for (int nt = 0; nt < 8; nt++)
                #pragma unroll
                for (int r = 0; r < 4; r++) s[mt][nt][r] = 0.0f;

        #pragma unroll
        for (int kk = 0; kk < 8; kk++) {
            unsigned af[2][4];
            #pragma unroll
            for (int mt = 0; mt < 2; mt++) {
                int r = qbase + mt*16 + g;
                af[mt][0] = __float_as_uint(Qs[r*QST     + kk*8 + t]);
                af[mt][1] = __float_as_uint(Qs[(r+8)*QST + kk*8 + t]);
                af[mt][2] = __float_as_uint(Qs[r*QST     + kk*8 + t + 4]);
                af[mt][3] = __float_as_uint(Qs[(r+8)*QST + kk*8 + t + 4]);
            }
            #pragma unroll
            for (int nt = 0; nt < 8; nt++) {
                unsigned bf[2];
                bf[0] = __float_as_uint(Ks[(nt*8+g)*KST + kk*8 + t]);
                bf[1] = __float_as_uint(Ks[(nt*8+g)*KST + kk*8 + t + 4]);
                mma8(s[0][nt], af[0], bf);
                mma8(s[1][nt], af[1], bf);
            }
        }

        // online softmax + P store (per m-tile)
        #pragma unroll
        for (int mt = 0; mt < 2; mt++) {
            float rm0 = -1e30f, rm1 = -1e30f;
            #pragma unroll
            for (int nt = 0; nt < 8; nt++) {
                rm0 = fmaxf(rm0, fmaxf(s[mt][nt][0], s[mt][nt][1]));
                rm1 = fmaxf(rm1, fmaxf(s[mt][nt][2], s[mt][nt][3]));
            }
            rm0 = fmaxf(rm0, __shfl_xor_sync(0xffffffffu, rm0, 1));
            rm0 = fmaxf(rm0, __shfl_xor_sync(0xffffffffu, rm0, 2));
            rm1 = fmaxf(rm1, __shfl_xor_sync(0xffffffffu, rm1, 1));
            rm1 = fmaxf(rm1, __shfl_xor_sync(0xffffffffu, rm1, 2));
            float mn0 = fmaxf(mA[mt][0], rm0), mn1 = fmaxf(mA[mt][1], rm1);
            float a0 = __expf(mA[mt][0] - mn0), a1 = __expf(mA[mt][1] - mn1);
            mA[mt][0] = mn0; mA[mt][1] = mn1;
            float rs0 = 0.0f, rs1 = 0.0f;
            #pragma unroll
            for (int nt = 0; nt < 8; nt++) {
                s[mt][nt][0] = __expf(s[mt][nt][0] - mn0); rs0 += s[mt][nt][0];
                s[mt][nt][1] = __expf(s[mt][nt][1] - mn0); rs0 += s[mt][nt][1];
                s[mt][nt][2] = __expf(s[mt][nt][2] - mn1); rs1 += s[mt][nt][2];
                s[mt][nt][3] = __expf(s[mt][nt][3] - mn1); rs1 += s[mt][nt][3];
            }
            rs0 += __shfl_xor_sync(0xffffffffu, rs0, 1);
            rs0 += __shfl_xor_sync(0xffffffffu, rs0, 2);
            rs1 += __shfl_xor_sync(0xffffffffu, rs1, 1);
            rs1 += __shfl_xor_sync(0xffffffffu, rs1, 2);
            lA[mt][0] = lA[mt][0]*a0 + rs0;
            lA[mt][1] = lA[mt][1]*a1 + rs1;
            #pragma unroll
            for (int dt = 0; dt < 8; dt++) {
                O[mt][dt][0] *= a0; O[mt][dt][1] *= a0;
                O[mt][dt][2] *= a1; O[mt][dt][3] *= a1;
            }
            int r = qbase + mt*16 + g;
            #pragma unroll
            for (int nt = 0; nt < 8; nt++) {
                float2 p0 = make_float2(f2tff(s[mt][nt][0]), f2tff(s[mt][nt][1]));
                float2 p1 = make_float2(f2tff(s[mt][nt][2]), f2tff(s[mt][nt][3]));
                *(float2*)&Ps[r*PST     + nt*8 + 2*t] = p0;
                *(float2*)&Ps[(r+8)*PST + nt*8 + 2*t] = p1;
            }
        }
        __syncwarp();

        // O += P V : shared V fragments across m-tiles
        #pragma unroll
        for (int jj = 0; jj < 8; jj++) {
            unsigned af[2][4];
            #pragma unroll
            for (int mt = 0; mt < 2; mt++) {
                int r = qbase + mt*16 + g;
                af[mt][0] = __float_as_uint(Ps[r*PST     + jj*8 + t]);
                af[mt][1] = __float_as_uint(Ps[(r+8)*PST + jj*8 + t]);
                af[mt][2] = __float_as_uint(Ps[r*PST     + jj*8 + t + 4]);
                af[mt][3] = __float_as_uint(Ps[(r+8)*PST + jj*8 + t + 4]);
            }
            #pragma unroll
            for (int dt = 0; dt < 8; dt++) {
                unsigned bf[2];
                bf[0] = __float_as_uint(Vs[(jj*8+t  )*VST + dt*8 + g]);
                bf[1] = __float_as_uint(Vs[(jj*8+t+4)*VST + dt*8 + g]);
                mma8(O[0][dt], af[0], bf);
                mma8(O[1][dt], af[1], bf);
            }
        }
    }

    // epilogue
    int b = bh / NH, h = bh - b*NH;
    #pragma unroll
    for (int mt = 0; mt < 2; mt++) {
        float inv0 = 1.0f/lA[mt][0], inv1 = 1.0f/lA[mt][1];
        int n = qt*256 + qbase + mt*16 + g;
        #pragma unroll
        for (int dt = 0; dt < 8; dt++) {
            int d = h*HD + dt*8 + 2*t;
            float2 va = make_float2(f2tff(O[mt][dt][0]*inv0), f2tff(O[mt][dt][1]*inv0));
            float2 vb = make_float2(f2tff(O[mt][dt][2]*inv1), f2tff(O[mt][dt][3]*inv1));
            *(float2*)(g_att + ((size_t)(b*SEQ + n))*DIM + d) = va;
            *(float2*)(g_att + ((size_t)(b*SEQ + n + 8))*DIM + d) = vb;
        }
    }
    #undef APREF
}

// ---------------- launch ----------------
extern "C" void kernel_launch(void* const* d_in, const int* in_sizes, int n_in,
                              void* d_out, int out_size) {
    const float* x     = (const float*)d_in[0];
    const float* gamma = (const float*)d_in[1];
    const float* beta  = (const float*)d_in[2];
    const float* Wqkv  = (const float*)d_in[3];
    const float* bqkv  = (const float*)d_in[4];
    const float* Wout  = (const float*)d_in[5];
    const float* bout  = (const float*)d_in[6];
    float* out = (float*)d_out;

    const int g1_smem = (128*36 + 32*264)*3*4;   // 156672
    const int g0_smem = (128*36 + 32*136)*3*4;   // 107520
    cudaFuncSetAttribute(gemm_kernel<1>, cudaFuncAttributeMaxDynamicSharedMemorySize, g1_smem);
    cudaFuncSetAttribute(gemm_kernel<0>, cudaFuncAttributeMaxDynamicSharedMemorySize, g0_smem);
    cudaFuncSetAttribute(attn_kernel,    cudaFuncAttributeMaxDynamicSharedMemorySize, ATTN_SMEM);

    wcvt_kernel<<<(DIM*3*DIM/4 + 255)/256, 256>>>((const float4*)Wqkv, DIM*3*DIM/4, 0);
    wcvt_kernel<<<(DIM*DIM/4   + 255)/256, 256>>>((const float4*)Wout, DIM*DIM/4,   1);

    ln_kernel<<<ROWS, 256>>>(x, gamma, beta);

    gemm_kernel<1><<<dim3((3*DIM)/256, ROWS/128), 256, g1_smem>>>(bqkv, nullptr, 3*DIM);

    attn_kernel<<<dim3(SEQ/256, BATCH*NH), 256, ATTN_SMEM>>>();

    gemm_kernel<0><<<dim3(DIM/128, ROWS/128), 128, g0_smem>>>(bout, out, DIM);
}

// round 8
// speedup vs baseline: 1.0919x; 1.0919x over previous
#include <cuda_runtime.h>
#include <cstdint>

#define DIM 768
#define NH 12
#define HD 64
#define BATCH 2
#define SEQ 2048
#define ROWS (BATCH*SEQ)      // 4096
#define SCALE 0.125f
#define LN_EPS 1e-5f

// ---------------- scratch (tf32-rounded payloads) ----------------
__device__ float g_xn[ROWS*DIM];
__device__ float g_q [BATCH*NH*SEQ*HD];   // [bh][n][d], pre-scaled by SCALE
__device__ float g_k [BATCH*NH*SEQ*HD];
__device__ float g_v [BATCH*NH*SEQ*HD];
__device__ float g_att[ROWS*DIM];
__device__ float g_wq[DIM*3*DIM];         // tf32-rounded W_qkv [K][N]
__device__ float g_wo[DIM*DIM];           // tf32-rounded W_out [K][N]

// ---------------- helpers ----------------
__device__ __forceinline__ unsigned f2tf(float x) {
    unsigned u; asm("cvt.rna.tf32.f32 %0, %1;" : "=r"(u) : "f"(x)); return u;
}
__device__ __forceinline__ float f2tff(float x) { return __uint_as_float(f2tf(x)); }

__device__ __forceinline__ void mma8(float* c, const unsigned* a, const unsigned* b) {
    asm volatile("mma.sync.aligned.m16n8k8.row.col.f32.tf32.tf32.f32 "
        "{%0,%1,%2,%3}, {%4,%5,%6,%7}, {%8,%9}, {%0,%1,%2,%3};"
        : "+f"(c[0]), "+f"(c[1]), "+f"(c[2]), "+f"(c[3])
        : "r"(a[0]), "r"(a[1]), "r"(a[2]), "r"(a[3]), "r"(b[0]), "r"(b[1]));
}

__device__ __forceinline__ void cp16(void* dst, const void* src) {
    unsigned d = (unsigned)__cvta_generic_to_shared(dst);
    asm volatile("cp.async.cg.shared.global [%0], [%1], 16;" :: "r"(d), "l"(src));
}
#define CPCOMMIT  asm volatile("cp.async.commit_group;" ::: "memory")
#define CPWAIT0   asm volatile("cp.async.wait_group 0;"  ::: "memory")
#define CPWAIT1   asm volatile("cp.async.wait_group 1;"  ::: "memory")

// ---------------- weight pre-convert (row-major, no transpose) ----------------
__global__ void wcvt_kernel(const float4* __restrict__ src, int n4, int which) {
    float4* dst = (float4*)(which ? g_wo : g_wq);
    int i = blockIdx.x * blockDim.x + threadIdx.x;
    if (i < n4) {
        float4 v = src[i];
        v.x = f2tff(v.x); v.y = f2tff(v.y); v.z = f2tff(v.z); v.w = f2tff(v.w);
        dst[i] = v;
    }
}

// ---------------- LayerNorm ----------------
__global__ void ln_kernel(const float* __restrict__ x,
                          const float* __restrict__ gamma,
                          const float* __restrict__ beta) {
    int row = blockIdx.x;
    const float* xr = x + (size_t)row * DIM;
    int t = threadIdx.x;
    float v0 = xr[t], v1 = xr[t+256], v2 = xr[t+512];
    __shared__ float red[8];

    float s = v0 + v1 + v2;
    #pragma unroll
    for (int o = 16; o > 0; o >>= 1) s += __shfl_xor_sync(0xffffffffu, s, o);
    if ((t & 31) == 0) red[t >> 5] = s;
    __syncthreads();
    if (t < 8) {
        float r = red[t];
        #pragma unroll
        for (int o = 4; o > 0; o >>= 1) r += __shfl_xor_sync(0xffu, r, o);
        if (t == 0) red[0] = r;
    }
    __syncthreads();
    float mean = red[0] * (1.0f / DIM);
    float d0 = v0 - mean, d1 = v1 - mean, d2 = v2 - mean;
    __syncthreads();

    float ss = d0*d0 + d1*d1 + d2*d2;
    #pragma unroll
    for (int o = 16; o > 0; o >>= 1) ss += __shfl_xor_sync(0xffffffffu, ss, o);
    if ((t & 31) == 0) red[t >> 5] = ss;
    __syncthreads();
    if (t < 8) {
        float r = red[t];
        #pragma unroll
        for (int o = 4; o > 0; o >>= 1) r += __shfl_xor_sync(0xffu, r, o);
        if (t == 0) red[0] = r;
    }
    __syncthreads();
    float rstd = rsqrtf(red[0] * (1.0f / DIM) + LN_EPS);

    float* o = g_xn + (size_t)row * DIM;
    o[t]     = f2tff(d0 * rstd * gamma[t]     + beta[t]);
    o[t+256] = f2tff(d1 * rstd * gamma[t+256] + beta[t+256]);
    o[t+512] = f2tff(d2 * rstd * gamma[t+512] + beta[t+512]);
}

// ---------------- TF32 mma.sync GEMM (R4 version, known-good) ----------------
// MODE 1: 128x256 block, 8 warps, A=g_xn B=g_wq -> scatter g_q/g_k/g_v
// MODE 0: 128x128 block, 4 warps, A=g_att B=g_wo -> C row-major
template<int MODE>
__global__ void __launch_bounds__(MODE ? 256 : 128, MODE ? 1 : 2)
gemm_kernel(const float* __restrict__ bias, float* __restrict__ C, int Ncols) {
    constexpr int T    = MODE ? 256 : 128;
    constexpr int BN   = MODE ? 256 : 128;
    constexpr int BSTR = BN + 8;
    constexpr int AS_STG = 128*36;
    constexpr int BS_STG = 32*BSTR;

    const float* A  = MODE ? g_xn : g_att;
    const float* Bm = MODE ? g_wq : g_wo;
    extern __shared__ __align__(16) float smg[];
    float* Asb = smg;
    float* Bsb = smg + 3*AS_STG;

    int tid = threadIdx.x;
    int wid = tid >> 5, lane = tid & 31;
    int g = lane >> 2, t = lane & 3;
    int wm = MODE ? (wid >> 2)*64 : (wid >> 1)*64;
    int wn = MODE ? (wid & 3)*64  : (wid & 1)*64;
    int m0 = blockIdx.y * 128, n0 = blockIdx.x * BN;

    float acc[4][8][4];
    #pragma unroll
    for (int i = 0; i < 4; i++)
        #pragma unroll
        for (int j = 0; j < 8; j++)
            #pragma unroll
            for (int r = 0; r < 4; r++) acc[i][j][r] = 0.0f;

    #define GPREF(k0, st) do { \
        _Pragma("unroll") \
        for (int l = 0; l < 1024/T; l++) { int idx = tid + l*T; int row = idx >> 3, cf = idx & 7; \
            cp16(Asb + (st)*AS_STG + row*36 + cf*4, A + (size_t)(m0+row)*DIM + (k0) + cf*4); } \
        _Pragma("unroll") \
        for (int l = 0; l < (8*BN)/T; l++) { int idx = tid + l*T; \
            int row = idx / (BN/4), cf = idx % (BN/4); \
            cp16(Bsb + (st)*BS_STG + row*BSTR + cf*4, Bm + (size_t)((k0)+row)*Ncols + n0 + cf*4); } \
    } while (0)

    GPREF(0, 0);  CPCOMMIT;
    GPREF(32, 1); CPCOMMIT;

    const int NK = DIM/32;   // 24
    for (int kt = 0; kt < NK; kt++) {
        CPWAIT1;
        __syncthreads();
        if (kt + 2 < NK) { int pst = (kt+2) % 3; GPREF((kt+2)*32, pst); }
        CPCOMMIT;

        int st = kt % 3;
        const float* Ast = Asb + st*AS_STG;
        const float* Bst = Bsb + st*BS_STG;

        #pragma unroll
        for (int ks = 0; ks < 4; ks++) {
            int kb = ks*8;
            unsigned af[4][4], bf[8][2];
            #pragma unroll
            for (int i = 0; i < 4; i++) {
                int r = wm + i*16 + g;
                af[i][0] = __float_as_uint(Ast[r*36     + kb+t  ]);
                af[i][1] = __float_as_uint(Ast[(r+8)*36 + kb+t  ]);
                af[i][2] = __float_as_uint(Ast[r*36     + kb+t+4]);
                af[i][3] = __float_as_uint(Ast[(r+8)*36 + kb+t+4]);
            }
            #pragma unroll
            for (int j = 0; j < 8; j++) {
                int c = wn + j*8 + g;
                bf[j][0] = __float_as_uint(Bst[(kb+t  )*BSTR + c]);
                bf[j][1] = __float_as_uint(Bst[(kb+t+4)*BSTR + c]);
            }
            #pragma unroll
            for (int i = 0; i < 4; i++)
                #pragma unroll
                for (int j = 0; j < 8; j++)
                    mma8(acc[i][j], af[i], bf[j]);
        }
        __syncthreads();
    }

    #pragma unroll
    for (int j = 0; j < 8; j++) {
        int c0 = n0 + wn + j*8 + 2*t;
        float b0 = bias[c0], b1 = bias[c0+1];
        if (MODE == 0) {
            #pragma unroll
            for (int i = 0; i < 4; i++) {
                int ra = m0 + wm + i*16 + g;
                float2 va = make_float2(acc[i][j][0] + b0, acc[i][j][1] + b1);
                float2 vb = make_float2(acc[i][j][2] + b0, acc[i][j][3] + b1);
                *(float2*)(C + (size_t)ra*Ncols + c0) = va;
                *(float2*)(C + (size_t)(ra+8)*Ncols + c0) = vb;
            }
        } else {
            int which = c0 / DIM;
            int cc = c0 - which*DIM;
            int h = cc >> 6, dd = cc & 63;
            float* dst = (which == 0) ? g_q : (which == 1) ? g_k : g_v;
            float mul = (which == 0) ? SCALE : 1.0f;
            #pragma unroll
            for (int i = 0; i < 4; i++) {
                int ra = m0 + wm + i*16 + g;
                int bb = ra >> 11, n = ra & 2047;
                size_t base = ((size_t)((bb*NH + h)*SEQ + n))*HD + dd;
                float2 va = make_float2(f2tff((acc[i][j][0] + b0)*mul),
                                        f2tff((acc[i][j][1] + b1)*mul));
                float2 vb = make_float2(f2tff((acc[i][j][2] + b0)*mul),
                                        f2tff((acc[i][j][3] + b1)*mul));
                *(float2*)(dst + base) = va;
                *(float2*)(dst + base + (size_t)8*HD) = vb;
            }
        }
    }
    #undef GPREF
}

// ---------------- pipelined TF32 flash attention ----------------
// 128q CTA, 8 warps x 16q, 64k tiles. Per body: QK(i+1) interleaved with PV(i).
// smem: Ps[128][68] (Q staging in prologue, then P buffer), K 2 stages, V 2 stages.
#define PST 68
#define KST 68
#define VST 72
#define KSTG (64*KST)   // 4352
#define VSTG (64*VST)   // 4608
#define ATTN_SMEM ((128*PST + 2*KSTG + 2*VSTG)*4)   // 106496 B

__global__ void __launch_bounds__(256, 2) attn_kernel() {
    extern __shared__ __align__(16) float sm[];
    float* Ps  = sm;                 // [128][68]
    float* Ksb = sm + 128*PST;       // [2][64][68]
    float* Vsb = Ksb + 2*KSTG;       // [2][64][72]

    int qt = blockIdx.x, bh = blockIdx.y;
    const float* Qg = g_q + (size_t)bh*SEQ*HD;
    const float* Kg = g_k + (size_t)bh*SEQ*HD;
    const float* Vg = g_v + (size_t)bh*SEQ*HD;

    int tid = threadIdx.x, wid = tid >> 5, lane = tid & 31;
    int g = lane >> 2, t = lane & 3;
    int r0 = wid*16 + g;

    #define LOADK(j) do { \
        _Pragma("unroll") \
        for (int l = 0; l < 4; l++) { int idx = tid + l*256; int row = idx >> 4, cf = idx & 15; \
            cp16(Ksb + ((j)&1)*KSTG + row*KST + cf*4, Kg + ((size_t)((j)*64+row))*HD + cf*4); } \
    } while (0)
    #define LOADV(j) do { \
        _Pragma("unroll") \
        for (int l = 0; l < 4; l++) { int idx = tid + l*256; int row = idx >> 4, cf = idx & 15; \
            cp16(Vsb + ((j)&1)*VSTG + row*VST + cf*4, Vg + ((size_t)((j)*64+row))*HD + cf*4); } \
    } while (0)

    // group A: Q -> Ps staging, K(0)
    #pragma unroll
    for (int l = 0; l < 8; l++) {
        int idx = tid + l*256;
        int row = idx >> 4, cf = idx & 15;
        cp16(Ps + row*PST + cf*4, Qg + ((size_t)(qt*128+row))*HD + cf*4);
    }
    LOADK(0);
    CPCOMMIT;
    // group B (= g_0): K(1), V(0)
    LOADK(1); LOADV(0);
    CPCOMMIT;
    CPWAIT1;              // group A done
    __syncthreads();

    // Q fragments -> registers (Ps becomes the P buffer afterwards)
    unsigned qf[8][4];
    #pragma unroll
    for (int kk = 0; kk < 8; kk++) {
        qf[kk][0] = __float_as_uint(Ps[r0*PST     + kk*8 + t]);
        qf[kk][1] = __float_as_uint(Ps[(r0+8)*PST + kk*8 + t]);
        qf[kk][2] = __float_as_uint(Ps[r0*PST     + kk*8 + t + 4]);
        qf[kk][3] = __float_as_uint(Ps[(r0+8)*PST + kk*8 + t + 4]);
    }

    float mr0 = -1e30f, mr1 = -1e30f, lr0 = 0.0f, lr1 = 0.0f;
    float O[8][4];
    #pragma unroll
    for (int dt = 0; dt < 8; dt++)
        #pragma unroll
        for (int r = 0; r < 4; r++) O[dt][r] = 0.0f;

    float s[8][4];

    // softmax on s + rescale O + store P (tf32) to own rows of Ps
    #define SOFTMAX_STORE() do { \
        float rm0 = -1e30f, rm1 = -1e30f; \
        _Pragma("unroll") \
        for (int nt = 0; nt < 8; nt++) { \
            rm0 = fmaxf(rm0, fmaxf(s[nt][0], s[nt][1])); \
            rm1 = fmaxf(rm1, fmaxf(s[nt][2], s[nt][3])); } \
        rm0 = fmaxf(rm0, __shfl_xor_sync(0xffffffffu, rm0, 1)); \
        rm0 = fmaxf(rm0, __shfl_xor_sync(0xffffffffu, rm0, 2)); \
        rm1 = fmaxf(rm1, __shfl_xor_sync(0xffffffffu, rm1, 1)); \
        rm1 = fmaxf(rm1, __shfl_xor_sync(0xffffffffu, rm1, 2)); \
        float mn0 = fmaxf(mr0, rm0), mn1 = fmaxf(mr1, rm1); \
        float a0 = __expf(mr0 - mn0), a1 = __expf(mr1 - mn1); \
        mr0 = mn0; mr1 = mn1; \
        float rs0 = 0.0f, rs1 = 0.0f; \
        _Pragma("unroll") \
        for (int nt = 0; nt < 8; nt++) { \
            s[nt][0] = __expf(s[nt][0] - mn0); rs0 += s[nt][0]; \
            s[nt][1] = __expf(s[nt][1] - mn0); rs0 += s[nt][1]; \
            s[nt][2] = __expf(s[nt][2] - mn1); rs1 += s[nt][2]; \
            s[nt][3] = __expf(s[nt][3] - mn1); rs1 += s[nt][3]; } \
        rs0 += __shfl_xor_sync(0xffffffffu, rs0, 1); \
        rs0 += __shfl_xor_sync(0xffffffffu, rs0, 2); \
        rs1 += __shfl_xor_sync(0xffffffffu, rs1, 1); \
        rs1 += __shfl_xor_sync(0xffffffffu, rs1, 2); \
        lr0 = lr0*a0 + rs0; lr1 = lr1*a1 + rs1; \
        _Pragma("unroll") \
        for (int dt = 0; dt < 8; dt++) { \
            O[dt][0] *= a0; O[dt][1] *= a0; \
            O[dt][2] *= a1; O[dt][3] *= a1; } \
        _Pragma("unroll") \
        for (int nt = 0; nt < 8; nt++) { \
            float2 p0 = make_float2(f2tff(s[nt][0]), f2tff(s[nt][1])); \
            float2 p1 = make_float2(f2tff(s[nt][2]), f2tff(s[nt][3])); \
            *(float2*)&Ps[r0*PST     + nt*8 + 2*t] = p0; \
            *(float2*)&Ps[(r0+8)*PST + nt*8 + 2*t] = p1; } \
        __syncwarp(); \
    } while (0)

    // prologue: QK(0) from K stage 0, then softmax(0) + P(0) store
    #pragma unroll
    for (int nt = 0; nt < 8; nt++)
        #pragma unroll
        for (int r = 0; r < 4; r++) s[nt][r] = 0.0f;
    {
        const float* Ks = Ksb;   // stage 0
        #pragma unroll
        for (int kk = 0; kk < 8; kk++) {
            #pragma unroll
            for (int nt = 0; nt < 8; nt++) {
                unsigned bf[2];
                bf[0] = __float_as_uint(Ks[(nt*8+g)*KST + kk*8 + t]);
                bf[1] = __float_as_uint(Ks[(nt*8+g)*KST + kk*8 + t + 4]);
                mma8(s[nt], qf[kk], bf);
            }
        }
    }
    SOFTMAX_STORE();

    const int NT = SEQ/64;   // 32
    // body(i): MMAs = QK(i+1) [K stage (i+1)&1] + PV(i) [V stage i&1]; then softmax(i+1).
    for (int i = 0; i < NT-1; i++) {
        CPWAIT0;             // g_i complete: K(i+1), V(i) resident
        __syncthreads();     // + all warps done with previous body's MMAs (stage reuse safe)
        if (i + 2 < NT) LOADK(i+2);
        LOADV(i+1);
        CPCOMMIT;            // g_{i+1}

        const float* Ks = Ksb + ((i+1)&1)*KSTG;
        const float* Vs = Vsb + (i&1)*VSTG;

        #pragma unroll
        for (int nt = 0; nt < 8; nt++)
            #pragma unroll
            for (int r = 0; r < 4; r++) s[nt][r] = 0.0f;

        #pragma unroll
        for (int u = 0; u < 8; u++) {
            // QK(i+1), k-group u
            #pragma unroll
            for (int nt = 0; nt < 8; nt++) {
                unsigned bf[2];
                bf[0] = __float_as_uint(Ks[(nt*8+g)*KST + u*8 + t]);
                bf[1] = __float_as_uint(Ks[(nt*8+g)*KST + u*8 + t + 4]);
                mma8(s[nt], qf[u], bf);
            }
            // PV(i), k-group u
            unsigned af[4];
            af[0] = __float_as_uint(Ps[r0*PST     + u*8 + t]);
            af[1] = __float_as_uint(Ps[(r0+8)*PST + u*8 + t]);
            af[2] = __float_as_uint(Ps[r0*PST     + u*8 + t + 4]);
            af[3] = __float_as_uint(Ps[(r0+8)*PST + u*8 + t + 4]);
            #pragma unroll
            for (int dt = 0; dt < 8; dt++) {
                unsigned bf[2];
                bf[0] = __float_as_uint(Vs[(u*8+t  )*VST + dt*8 + g]);
                bf[1] = __float_as_uint(Vs[(u*8+t+4)*VST + dt*8 + g]);
                mma8(O[dt], af, bf);
            }
        }
        SOFTMAX_STORE();     // softmax(i+1), stores P(i+1)
    }

    // epilogue: PV(NT-1)
    CPWAIT0;
    __syncthreads();
    {
        const float* Vs = Vsb + ((NT-1)&1)*VSTG;
        #pragma unroll
        for (int u = 0; u < 8; u++) {
            unsigned af[4];
            af[0] = __float_as_uint(Ps[r0*PST     + u*8 + t]);
            af[1] = __float_as_uint(Ps[(r0+8)*PST + u*8 + t]);
            af[2] = __float_as_uint(Ps[r0*PST     + u*8 + t + 4]);
            af[3] = __float_as_uint(Ps[(r0+8)*PST + u*8 + t + 4]);
            #pragma unroll
            for (int dt = 0; dt < 8; dt++) {
                unsigned bf[2];
                bf[0] = __float_as_uint(Vs[(u*8+t  )*VST + dt*8 + g]);
                bf[1] = __float_as_uint(Vs[(u*8+t+4)*VST + dt*8 + g]);
                mma8(O[dt], af, bf);
            }
        }
    }

    // normalize, tf32-round, write [B,N,D]
    int b = bh / NH, h = bh - b*NH;
    float inv0 = 1.0f/lr0, inv1 = 1.0f/lr1;
    int n = qt*128 + r0;
    #pragma unroll
    for (int dt = 0; dt < 8; dt++) {
        int d = h*HD + dt*8 + 2*t;
        float2 va = make_float2(f2tff(O[dt][0]*inv0), f2tff(O[dt][1]*inv0));
        float2 vb = make_float2(f2tff(O[dt][2]*inv1), f2tff(O[dt][3]*inv1));
        *(float2*)(g_att + ((size_t)(b*SEQ + n))*DIM + d) = va;
        *(float2*)(g_att + ((size_t)(b*SEQ + n + 8))*DIM + d) = vb;
    }
    #undef LOADK
    #undef LOADV
    #undef SOFTMAX_STORE
}

// ---------------- launch ----------------
extern "C" void kernel_launch(void* const* d_in, const int* in_sizes, int n_in,
                              void* d_out, int out_size) {
    const float* x     = (const float*)d_in[0];
    const float* gamma = (const float*)d_in[1];
    const float* beta  = (const float*)d_in[2];
    const float* Wqkv  = (const float*)d_in[3];
    const float* bqkv  = (const float*)d_in[4];
    const float* Wout  = (const float*)d_in[5];
    const float* bout  = (const float*)d_in[6];
    float* out = (float*)d_out;

    const int g1_smem = (128*36 + 32*264)*3*4;   // 156672
    const int g0_smem = (128*36 + 32*136)*3*4;   // 107520
    cudaFuncSetAttribute(gemm_kernel<1>, cudaFuncAttributeMaxDynamicSharedMemorySize, g1_smem);
    cudaFuncSetAttribute(gemm_kernel<0>, cudaFuncAttributeMaxDynamicSharedMemorySize, g0_smem);
    cudaFuncSetAttribute(attn_kernel,    cudaFuncAttributeMaxDynamicSharedMemorySize, ATTN_SMEM);

    wcvt_kernel<<<(DIM*3*DIM/4 + 255)/256, 256>>>((const float4*)Wqkv, DIM*3*DIM/4, 0);
    wcvt_kernel<<<(DIM*DIM/4   + 255)/256, 256>>>((const float4*)Wout, DIM*DIM/4,   1);

    ln_kernel<<<ROWS, 256>>>(x, gamma, beta);

    gemm_kernel<1><<<dim3((3*DIM)/256, ROWS/128), 256, g1_smem>>>(bqkv, nullptr, 3*DIM);

    attn_kernel<<<dim3(SEQ/128, BATCH*NH), 256, ATTN_SMEM>>>();

    gemm_kernel<0><<<dim3(DIM/128, ROWS/128), 128, g0_smem>>>(bout, out, DIM);
}